// round 14
// baseline (speedup 1.0000x reference)
#include <cuda_runtime.h>
#include <math.h>

#define N_IMG   4
#define M_ANCH  250000
#define C_CLS   80
#define PER_IMG (M_ANCH * C_CLS)      // 20,000,000 per image
#define KTOP    4000                  // PRE_NMS_TOP_N * 2 * 2
#define POST    100
#define NBINS   4096
#define CAPC    (1 << 18)             // candidate cap per image
#define SORTN   4096                  // selected-set sort width
#define BNDC    4096                  // boundary-bin cap
#define SUBC    512                   // sub-boundary cap
#define SBUF    3584                  // per-block staging buffer
#define CMPI    0x3EFFFFFF            // (int)bits > CMPI  <=>  float >= 0.5 (positive)
#define BBOX_CLIP 4.135166556742356f

#define PREP_SMEM (SORTN * 8 + BNDC * 8)          // 65536 B
#define FINT    512                                // k_fin threads (16 warps)
#define CCAP    256                                // per-class list capacity
#define RPC     (CCAP / 32)                        // 8 items per lane
// k_fin smem: lbv 16000 | cl 40960 | ccnt 320 | surv 4000 | ps 2048
#define FIN_SMEM (KTOP * 4 + C_CLS * CCAP * 2 + C_CLS * 4 + KTOP + FINT * 4)

// -------- device scratch --------
__device__ unsigned           g_hist[N_IMG][NBINS];
__device__ int                g_cnt[N_IMG];
__device__ int                g_tb[N_IMG];
__device__ unsigned long long g_cand[N_IMG][CAPC];
// decoded, sorted top-KTOP per image
__device__ float gbx1[N_IMG][KTOP], gby1[N_IMG][KTOP], gbx2[N_IMG][KTOP],
                 gby2[N_IMG][KTOP], gbar[N_IMG][KTOP], gbso[N_IMG][KTOP];
__device__ int   gblb[N_IMG][KTOP];

__device__ __forceinline__ float keyfloat(unsigned k) {
    return __uint_as_float((k & 0x80000000u) ? (k & 0x7FFFFFFFu) : ~k);
}

// -------- kernel 0: zero scratch (unchanged) --------
__global__ void k_zero() {
    int i = blockIdx.x * blockDim.x + threadIdx.x;
    if (i < N_IMG * NBINS) (&g_hist[0][0])[i] = 0u;
    if (i < N_IMG) { g_cnt[i] = 0; g_tb[i] = 0; }
}

// -------- kernel 1: fast streaming filter (R8/R9 verbatim) --------
__global__ void __launch_bounds__(1024) k_scan(const uint4* __restrict__ cls) {
    int img = blockIdx.y;
    __shared__ unsigned sh[NBINS];
    __shared__ unsigned long long sbuf[SBUF];
    __shared__ int s_cnt, s_base;
    for (int i = threadIdx.x; i < NBINS; i += 1024) sh[i] = 0u;
    if (threadIdx.x == 0) s_cnt = 0;
    __syncthreads();

    const uint4* p = cls + (size_t)img * (PER_IMG / 4);
    const int NV = PER_IMG / 4;
    const int NF = (NV / 4096) * 4096;

    auto emit = [&](unsigned u, unsigned e) {
        unsigned key = u | 0x80000000u;
        atomicAdd(&sh[key >> 20], 1u);
        unsigned long long cd = ((unsigned long long)key << 32)
                              | (unsigned long long)(0xFFFFFFFFu - e);
        int pos = atomicAdd(&s_cnt, 1);
        if (pos < SBUF) sbuf[pos] = cd;
        else {
            int gp = atomicAdd(&g_cnt[img], 1);
            if (gp < CAPC) g_cand[img][gp] = cd;
        }
    };

    for (int base = blockIdx.x * 4096; base < NF; base += gridDim.x * 4096) {
        int i0 = base + threadIdx.x;
        uint4 a = __ldcs(p + i0);
        uint4 b = __ldcs(p + i0 + 1024);
        uint4 c = __ldcs(p + i0 + 2048);
        uint4 d = __ldcs(p + i0 + 3072);
        int mi = max(max(max((int)a.x, (int)a.y), max((int)a.z, (int)a.w)),
                     max(max((int)b.x, (int)b.y), max((int)b.z, (int)b.w)));
        float mf = fmaxf(
            fmaxf(fmaxf(__uint_as_float(c.x), __uint_as_float(c.y)),
                  fmaxf(__uint_as_float(c.z), __uint_as_float(c.w))),
            fmaxf(fmaxf(__uint_as_float(d.x), __uint_as_float(d.y)),
                  fmaxf(__uint_as_float(d.z), __uint_as_float(d.w))));
        if (mi > CMPI || mf > 0.5f) {
            uint4 vs[4] = {a, b, c, d};
            #pragma unroll
            for (int k = 0; k < 4; k++) {
                unsigned arr[4] = {vs[k].x, vs[k].y, vs[k].z, vs[k].w};
                int iv = i0 + k * 1024;
                #pragma unroll
                for (int j = 0; j < 4; j++)
                    if ((int)arr[j] > CMPI) emit(arr[j], (unsigned)(iv * 4 + j));
            }
        }
    }
    for (int i = NF + blockIdx.x * 1024 + threadIdx.x; i < NV; i += gridDim.x * 1024) {
        uint4 v = __ldcs(p + i);
        unsigned arr[4] = {v.x, v.y, v.z, v.w};
        #pragma unroll
        for (int j = 0; j < 4; j++)
            if ((int)arr[j] > CMPI) emit(arr[j], (unsigned)(i * 4 + j));
    }
    __syncthreads();

    int n = s_cnt; if (n > SBUF) n = SBUF;
    if (threadIdx.x == 0) s_base = atomicAdd(&g_cnt[img], n);
    __syncthreads();
    int gbase = s_base;
    for (int i = threadIdx.x; i < n; i += 1024) {
        int pos = gbase + i;
        if (pos < CAPC) g_cand[img][pos] = sbuf[i];
    }
    for (int i = threadIdx.x; i < NBINS; i += 1024) {
        unsigned cnum = sh[i];
        if (cnum) atomicAdd(&g_hist[img][i], cnum);
    }
}

// -------- kernel 2: suffix scan -> threshold bin (unchanged) --------
__global__ void __launch_bounds__(1024) k_sel() {
    int img = blockIdx.x;
    int tid = threadIdx.x;
    __shared__ unsigned part[1024];

    unsigned local[4];
    unsigned s = 0;
    #pragma unroll
    for (int q = 0; q < 4; q++) {
        int r = tid * 4 + q;
        unsigned v = g_hist[img][NBINS - 1 - r];
        local[q] = v; s += v;
    }
    part[tid] = s;
    __syncthreads();
    for (int off = 1; off < 1024; off <<= 1) {
        unsigned v = part[tid];
        unsigned add = (tid >= off) ? part[tid - off] : 0u;
        __syncthreads();
        part[tid] = v + add;
        __syncthreads();
    }
    unsigned cum = part[tid] - s;
    #pragma unroll
    for (int q = 0; q < 4; q++) {
        unsigned prev = cum;
        cum += local[q];
        if (prev < (unsigned)KTOP && cum >= (unsigned)KTOP) {
            g_tb[img] = NBINS - 1 - (tid * 4 + q);
        }
    }
}

// -------- kernel 3: select + sort + decode -> global (NMS removed) --------
__global__ void __launch_bounds__(1024) k_prep(const float* __restrict__ reg,
                                               const float* __restrict__ anc) {
    extern __shared__ unsigned char dyn[];
    unsigned long long* sb  = (unsigned long long*)dyn;               // [SORTN]
    unsigned long long* bnd = (unsigned long long*)(dyn + SORTN * 8); // [BNDC]

    __shared__ int s_n, s_b, s_sub, s_st, s_nab;
    __shared__ unsigned h2[256], p2[256];
    __shared__ unsigned long long subarr[SUBC];

    int img = blockIdx.x;
    int tid = threadIdx.x;
    if (tid == 0) { s_n = 0; s_b = 0; s_sub = 0; s_st = -1; s_nab = 0; }
    if (tid < 256) h2[tid] = 0u;
    for (int i = tid; i < SORTN; i += 1024) sb[i] = 0ULL;
    __syncthreads();

    // Phase 1: definite (bin > tb) -> sb; boundary (bin == tb) -> bnd
    int C = g_cnt[img]; if (C > CAPC) C = CAPC;
    unsigned tb = (unsigned)g_tb[img];
    for (int i = tid; i < C; i += 1024) {
        unsigned long long cd = g_cand[img][i];
        unsigned key = (unsigned)(cd >> 32);
        unsigned bin = key >> 20;
        if (bin > tb) {
            int pos = atomicAdd(&s_n, 1);
            if (pos < SORTN) sb[pos] = cd;
        } else if (bin == tb) {
            int bp = atomicAdd(&s_b, 1);
            if (bp < BNDC) {
                bnd[bp] = cd;
                atomicAdd(&h2[(key >> 12) & 0xFFu], 1u);
            }
        }
    }
    __syncthreads();

    // Phase 2: sub-bin refine within boundary bin
    int n_def = s_n; if (n_def > SORTN) n_def = SORTN;
    int need = KTOP - n_def; if (need < 0) need = 0;
    int nb = s_b; if (nb > BNDC) nb = BNDC;
    unsigned myv = 0;
    if (tid < 256) { myv = h2[255 - tid]; p2[tid] = myv; }
    __syncthreads();
    for (int off = 1; off < 256; off <<= 1) {
        unsigned v = 0, add = 0;
        if (tid < 256) { v = p2[tid]; if (tid >= off) add = p2[tid - off]; }
        __syncthreads();
        if (tid < 256) p2[tid] = v + add;
        __syncthreads();
    }
    if (need > 0 && tid < 256) {
        unsigned cum = p2[tid];
        unsigned prev = cum - myv;
        if (prev < (unsigned)need && cum >= (unsigned)need) {
            s_st = 255 - tid;
            s_nab = (int)prev;
        }
    }
    __syncthreads();
    int st = s_st, nab = s_nab;
    int need_sub = need - nab;
    if (need > 0) {
        for (int i = tid; i < nb; i += 1024) {
            unsigned long long cd = bnd[i];
            int sub = (int)(((unsigned)(cd >> 32) >> 12) & 0xFFu);
            if (sub > st) {
                int pos = atomicAdd(&s_n, 1);
                if (pos < SORTN) sb[pos] = cd;
            } else if (sub == st) {
                int q = atomicAdd(&s_sub, 1);
                if (q < SUBC) subarr[q] = cd;
            }
        }
        __syncthreads();
        int ms = s_sub; if (ms > SUBC) ms = SUBC;
        for (int i = tid; i < ms; i += 1024) {
            unsigned long long cd = subarr[i];
            int r = 0;
            for (int k = 0; k < ms; k++) r += (subarr[k] > cd) ? 1 : 0;
            if (r < need_sub) {
                int pos = atomicAdd(&s_n, 1);
                if (pos < SORTN) sb[pos] = cd;
            }
        }
    }
    __syncthreads();

    // bitonic sort descending over SORTN (pads = 0 sink to the bottom)
    for (int kk = 2; kk <= SORTN; kk <<= 1) {
        for (int jj = kk >> 1; jj > 0; jj >>= 1) {
            for (int i = tid; i < SORTN; i += 1024) {
                int l = i ^ jj;
                if (l > i) {
                    unsigned long long a = sb[i], b = sb[l];
                    bool desc = ((i & kk) == 0);
                    if (desc ? (a < b) : (a > b)) { sb[i] = b; sb[l] = a; }
                }
            }
            __syncthreads();
        }
    }

    // decode top-KTOP in sorted (descending) order -> global arrays
    for (int i = tid; i < KTOP; i += 1024) {
        unsigned long long cd = sb[i];
        unsigned key = (unsigned)(cd >> 32);
        if (key == 0u) {
            gbx1[img][i] = 0.f; gby1[img][i] = 0.f; gbx2[img][i] = 0.f; gby2[img][i] = 0.f;
            gbar[img][i] = 0.f; gbso[img][i] = 0.f; gblb[img][i] = -1;
            continue;
        }
        unsigned e = 0xFFFFFFFFu - (unsigned)(cd & 0xFFFFFFFFu);
        int labv = (int)(e % C_CLS);
        int bidx = (int)(e / C_CLS);
        float logit = keyfloat(key);
        float score = 1.f / (1.f + expf(-logit));
        float4 A = *(const float4*)(anc + ((size_t)img * M_ANCH + bidx) * 4);
        float4 R = *(const float4*)(reg + ((size_t)img * M_ANCH + bidx) * 4);
        float wdt = A.z - A.x + 1.f;
        float hgt = A.w - A.y + 1.f;
        float cx = A.x + 0.5f * wdt;
        float cy = A.y + 0.5f * hgt;
        float dx = R.x / 10.f;
        float dy = R.y / 10.f;
        float dw = fminf(R.z / 5.f, BBOX_CLIP);
        float dh = fminf(R.w / 5.f, BBOX_CLIP);
        float pcx = dx * wdt + cx;
        float pcy = dy * hgt + cy;
        float pw = expf(dw) * wdt;
        float ph = expf(dh) * hgt;
        float bx1 = pcx - 0.5f * pw;
        float by1 = pcy - 0.5f * ph;
        float bx2 = pcx + 0.5f * pw - 1.f;
        float by2 = pcy + 0.5f * ph - 1.f;
        gbx1[img][i] = bx1; gby1[img][i] = by1; gbx2[img][i] = bx2; gby2[img][i] = by2;
        gbar[img][i] = fmaxf(bx2 - bx1, 0.f) * fmaxf(by2 - by1, 0.f);
        gbso[img][i] = score;
        gblb[img][i] = (score > 0.05f) ? labv : -1;   // ineligible excluded entirely
    }
}

// -------- kernel 4: class-parallel exact NMS + compact + output --------
// Equivalence: suppression is class-local => global greedy kept set ==
// union of per-class greedy survivors; kept order == survivors in
// sorted-index-ascending order, first POST.
__global__ void __launch_bounds__(FINT) k_fin(const int* __restrict__ sizes,
                                              float* __restrict__ out) {
    extern __shared__ unsigned char dyn2[];
    int*            lbv  = (int*)dyn2;                                    // [KTOP]
    unsigned short* cl   = (unsigned short*)(dyn2 + KTOP * 4);            // [C_CLS*CCAP]
    int*            ccnt = (int*)(dyn2 + KTOP * 4 + C_CLS * CCAP * 2);    // [C_CLS]
    unsigned char*  surv = (unsigned char*)((char*)ccnt + C_CLS * 4);     // [KTOP]
    int*            ps   = (int*)((char*)surv + KTOP);                    // [FINT]

    __shared__ int keepj[POST];
    __shared__ int s_tot;

    int img = blockIdx.x;
    int tid = threadIdx.x;
    int warp = tid >> 5, lane = tid & 31;

    for (int i = tid; i < KTOP; i += FINT) { lbv[i] = gblb[img][i]; surv[i] = 0; }
    if (tid < C_CLS) ccnt[tid] = 0;
    __syncthreads();

    // stable class bucketing: one warp per class (order-preserving ballot scan)
    for (int c = warp; c < C_CLS; c += FINT / 32) {
        int cnt = 0;
        for (int base = 0; base < KTOP; base += 32) {
            bool m = (lbv[base + lane] == c);
            unsigned bal = __ballot_sync(0xFFFFFFFFu, m);
            if (m) {
                int rk = __popc(bal & ((1u << lane) - 1u));
                int pos = cnt + rk;
                if (pos < CCAP) cl[c * CCAP + pos] = (unsigned short)(base + lane);
            }
            cnt += __popc(bal);
        }
        if (lane == 0) ccnt[c] = (cnt < CCAP) ? cnt : CCAP;
    }
    __syncthreads();

    // per-class greedy NMS (warp per class; items in registers, desc-score order)
    for (int c = warp; c < C_CLS; c += FINT / 32) {
        int m = ccnt[c];
        if (m == 0) continue;
        int   id[RPC];
        float lx1[RPC], ly1[RPC], lx2[RPC], ly2[RPC], lar[RPC];
        unsigned alive = 0u;
        #pragma unroll
        for (int r = 0; r < RPC; r++) {
            int p = lane + 32 * r;
            id[r] = 0; lx1[r] = 0.f; ly1[r] = 0.f; lx2[r] = 0.f; ly2[r] = 0.f; lar[r] = 0.f;
            if (p < m) {
                int i = (int)cl[c * CCAP + p];
                id[r] = i;
                lx1[r] = gbx1[img][i]; ly1[r] = gby1[img][i];
                lx2[r] = gbx2[img][i]; ly2[r] = gby2[img][i];
                lar[r] = gbar[img][i];
                alive |= (1u << r);
            }
        }
        while (true) {
            int myp = 0x7FFFFFFF;
            #pragma unroll
            for (int r = RPC - 1; r >= 0; r--)
                if (alive & (1u << r)) myp = lane + 32 * r;   // smallest alive p for lane
            int wmin = myp;
            #pragma unroll
            for (int o = 16; o > 0; o >>= 1)
                wmin = min(wmin, __shfl_xor_sync(0xFFFFFFFFu, wmin, o));
            if (wmin == 0x7FFFFFFF) break;
            int sl = wmin & 31, sr = wmin >> 5;
            float tx1 = 0.f, ty1 = 0.f, tx2 = 0.f, ty2 = 0.f, tar = 0.f;
            #pragma unroll
            for (int r = 0; r < RPC; r++)
                if (r == sr) { tx1 = lx1[r]; ty1 = ly1[r]; tx2 = lx2[r]; ty2 = ly2[r]; tar = lar[r]; }
            float sx1 = __shfl_sync(0xFFFFFFFFu, tx1, sl);
            float sy1 = __shfl_sync(0xFFFFFFFFu, ty1, sl);
            float sx2 = __shfl_sync(0xFFFFFFFFu, tx2, sl);
            float sy2 = __shfl_sync(0xFFFFFFFFu, ty2, sl);
            float sar = __shfl_sync(0xFFFFFFFFu, tar, sl);
            if (lane == sl) { alive &= ~(1u << sr); surv[id[sr]] = 1; }
            #pragma unroll
            for (int r = 0; r < RPC; r++) {
                if (alive & (1u << r)) {
                    float xx1 = fmaxf(sx1, lx1[r]);
                    float yy1 = fmaxf(sy1, ly1[r]);
                    float xx2 = fminf(sx2, lx2[r]);
                    float yy2 = fminf(sy2, ly2[r]);
                    float inter = fmaxf(xx2 - xx1, 0.f) * fmaxf(yy2 - yy1, 0.f);
                    float iou = inter / (sar + lar[r] - inter + 1e-6f);
                    if (iou > 0.5f) alive &= ~(1u << r);
                }
            }
        }
    }
    __syncthreads();

    // stable compact: rank survivors in sorted order, keep first POST
    const int IPT = (KTOP + FINT - 1) / FINT;   // 8
    int cnt = 0;
    #pragma unroll
    for (int k = 0; k < IPT; k++) {
        int i = tid * IPT + k;
        if (i < KTOP && surv[i]) cnt++;
    }
    ps[tid] = cnt;
    __syncthreads();
    for (int off = 1; off < FINT; off <<= 1) {
        int v = ps[tid];
        int add = (tid >= off) ? ps[tid - off] : 0;
        __syncthreads();
        ps[tid] = v + add;
        __syncthreads();
    }
    int rk = ps[tid] - cnt;
    #pragma unroll
    for (int k = 0; k < IPT; k++) {
        int i = tid * IPT + k;
        if (i < KTOP && surv[i]) {
            if (rk < POST) keepj[rk] = i;
            rk++;
        }
    }
    if (tid == FINT - 1) {
        int tot = ps[FINT - 1];
        s_tot = (tot < POST) ? tot : POST;
    }
    __syncthreads();

    // outputs: boxes[4,100,4] | scores[4,100] | classes[4,100] | num[4]
    float wImg = (float)sizes[img * 2 + 0];
    float hImg = (float)sizes[img * 2 + 1];
    if (tid < POST) {
        int t = tid;
        int ok = (t < s_tot) ? 1 : 0;
        float b0, b1, b2, b3, s, c;
        if (ok) {
            int j = keepj[t];
            b0 = fminf(fmaxf(gbx1[img][j], 0.f), wImg - 1.f);
            b1 = fminf(fmaxf(gby1[img][j], 0.f), hImg - 1.f);
            b2 = fminf(fmaxf(gbx2[img][j], 0.f), wImg - 1.f);
            b3 = fminf(fmaxf(gby2[img][j], 0.f), hImg - 1.f);
            s = gbso[img][j];
            c = (float)(gblb[img][j] + 1);
        } else {
            b0 = b1 = b2 = b3 = 0.f; s = 0.f; c = -1.f;
        }
        float* ob = out + (size_t)img * POST * 4;
        ob[t * 4 + 0] = b0; ob[t * 4 + 1] = b1; ob[t * 4 + 2] = b2; ob[t * 4 + 3] = b3;
        out[N_IMG * POST * 4 + img * POST + t] = s;
        out[N_IMG * POST * 4 + N_IMG * POST + img * POST + t] = c;
    }
    if (tid == 0) {
        out[N_IMG * POST * 4 + 2 * N_IMG * POST + img] = (float)s_tot;
    }
}

extern "C" void kernel_launch(void* const* d_in, const int* in_sizes, int n_in,
                              void* d_out, int out_size) {
    const float* cls  = (const float*)d_in[0];
    const float* regr = (const float*)d_in[1];
    const float* anch = (const float*)d_in[2];
    const int*   szs  = (const int*)d_in[3];
    float* out = (float*)d_out;

    static bool attr_done = false;
    if (!attr_done) {
        cudaFuncSetAttribute(k_prep, cudaFuncAttributeMaxDynamicSharedMemorySize, PREP_SMEM);
        cudaFuncSetAttribute(k_fin,  cudaFuncAttributeMaxDynamicSharedMemorySize, FIN_SMEM);
        attr_done = true;
    }

    k_zero<<<(N_IMG * NBINS + 255) / 256, 256>>>();
    k_scan<<<dim3(74, N_IMG), 1024>>>((const uint4*)cls);
    k_sel<<<N_IMG, 1024>>>();
    k_prep<<<N_IMG, 1024, PREP_SMEM>>>(regr, anch);
    k_fin<<<N_IMG, FINT, FIN_SMEM>>>(szs, out);
}

// round 15
// speedup vs baseline: 1.8395x; 1.8395x over previous
#include <cuda_runtime.h>
#include <math.h>

#define N_IMG   4
#define M_ANCH  250000
#define C_CLS   80
#define PER_IMG (M_ANCH * C_CLS)      // 20,000,000 per image
#define KTOP    4000                  // PRE_NMS_TOP_N * 2 * 2
#define POST    100
#define NBINS   4096
#define CAPC    (1 << 18)             // candidate cap per image
#define SORTN   4096                  // selected-set sort width
#define BNDC    4096                  // boundary-bin cap
#define SUBC    512                   // sub-boundary cap
#define SBUF    3584                  // per-block staging buffer
#define CMPI    0x3EFFFFFF            // (int)bits > CMPI  <=>  float >= 0.5 (positive)
#define BBOX_CLIP 4.135166556742356f

#define PREP_SMEM (SORTN * 8 + BNDC * 8)          // 65536 B (bnd region reused as lbv)
#define CCAP    256                                // per-class list capacity
#define RPC     (CCAP / 32)                        // 8 items per lane

// -------- device scratch --------
__device__ unsigned           g_hist[N_IMG][NBINS];
__device__ int                g_cnt[N_IMG];
__device__ int                g_tb[N_IMG];
__device__ unsigned long long g_cand[N_IMG][CAPC];
// decoded, sorted top-KTOP per image
__device__ float gbx1[N_IMG][KTOP], gby1[N_IMG][KTOP], gbx2[N_IMG][KTOP],
                 gby2[N_IMG][KTOP], gbar[N_IMG][KTOP], gbso[N_IMG][KTOP];
__device__ int   gblb[N_IMG][KTOP];
// class lists + survivor flags
__device__ unsigned short g_cl[N_IMG][C_CLS][CCAP];
__device__ int            g_ccnt[N_IMG][C_CLS];
__device__ unsigned char  g_surv[N_IMG][KTOP];

__device__ __forceinline__ float keyfloat(unsigned k) {
    return __uint_as_float((k & 0x80000000u) ? (k & 0x7FFFFFFFu) : ~k);
}

// -------- kernel 0: zero scratch --------
__global__ void k_zero() {
    int i = blockIdx.x * blockDim.x + threadIdx.x;
    if (i < N_IMG * NBINS) (&g_hist[0][0])[i] = 0u;
    if (i < N_IMG) { g_cnt[i] = 0; g_tb[i] = 0; }
}

// -------- kernel 1: fast streaming filter (R8/R9 verbatim) --------
__global__ void __launch_bounds__(1024) k_scan(const uint4* __restrict__ cls) {
    int img = blockIdx.y;
    __shared__ unsigned sh[NBINS];
    __shared__ unsigned long long sbuf[SBUF];
    __shared__ int s_cnt, s_base;
    for (int i = threadIdx.x; i < NBINS; i += 1024) sh[i] = 0u;
    if (threadIdx.x == 0) s_cnt = 0;
    __syncthreads();

    const uint4* p = cls + (size_t)img * (PER_IMG / 4);
    const int NV = PER_IMG / 4;
    const int NF = (NV / 4096) * 4096;

    auto emit = [&](unsigned u, unsigned e) {
        unsigned key = u | 0x80000000u;
        atomicAdd(&sh[key >> 20], 1u);
        unsigned long long cd = ((unsigned long long)key << 32)
                              | (unsigned long long)(0xFFFFFFFFu - e);
        int pos = atomicAdd(&s_cnt, 1);
        if (pos < SBUF) sbuf[pos] = cd;
        else {
            int gp = atomicAdd(&g_cnt[img], 1);
            if (gp < CAPC) g_cand[img][gp] = cd;
        }
    };

    for (int base = blockIdx.x * 4096; base < NF; base += gridDim.x * 4096) {
        int i0 = base + threadIdx.x;
        uint4 a = __ldcs(p + i0);
        uint4 b = __ldcs(p + i0 + 1024);
        uint4 c = __ldcs(p + i0 + 2048);
        uint4 d = __ldcs(p + i0 + 3072);
        int mi = max(max(max((int)a.x, (int)a.y), max((int)a.z, (int)a.w)),
                     max(max((int)b.x, (int)b.y), max((int)b.z, (int)b.w)));
        float mf = fmaxf(
            fmaxf(fmaxf(__uint_as_float(c.x), __uint_as_float(c.y)),
                  fmaxf(__uint_as_float(c.z), __uint_as_float(c.w))),
            fmaxf(fmaxf(__uint_as_float(d.x), __uint_as_float(d.y)),
                  fmaxf(__uint_as_float(d.z), __uint_as_float(d.w))));
        if (mi > CMPI || mf > 0.5f) {
            uint4 vs[4] = {a, b, c, d};
            #pragma unroll
            for (int k = 0; k < 4; k++) {
                unsigned arr[4] = {vs[k].x, vs[k].y, vs[k].z, vs[k].w};
                int iv = i0 + k * 1024;
                #pragma unroll
                for (int j = 0; j < 4; j++)
                    if ((int)arr[j] > CMPI) emit(arr[j], (unsigned)(iv * 4 + j));
            }
        }
    }
    for (int i = NF + blockIdx.x * 1024 + threadIdx.x; i < NV; i += gridDim.x * 1024) {
        uint4 v = __ldcs(p + i);
        unsigned arr[4] = {v.x, v.y, v.z, v.w};
        #pragma unroll
        for (int j = 0; j < 4; j++)
            if ((int)arr[j] > CMPI) emit(arr[j], (unsigned)(i * 4 + j));
    }
    __syncthreads();

    int n = s_cnt; if (n > SBUF) n = SBUF;
    if (threadIdx.x == 0) s_base = atomicAdd(&g_cnt[img], n);
    __syncthreads();
    int gbase = s_base;
    for (int i = threadIdx.x; i < n; i += 1024) {
        int pos = gbase + i;
        if (pos < CAPC) g_cand[img][pos] = sbuf[i];
    }
    for (int i = threadIdx.x; i < NBINS; i += 1024) {
        unsigned cnum = sh[i];
        if (cnum) atomicAdd(&g_hist[img][i], cnum);
    }
}

// -------- kernel 2: suffix scan -> threshold bin (unchanged) --------
__global__ void __launch_bounds__(1024) k_sel() {
    int img = blockIdx.x;
    int tid = threadIdx.x;
    __shared__ unsigned part[1024];

    unsigned local[4];
    unsigned s = 0;
    #pragma unroll
    for (int q = 0; q < 4; q++) {
        int r = tid * 4 + q;
        unsigned v = g_hist[img][NBINS - 1 - r];
        local[q] = v; s += v;
    }
    part[tid] = s;
    __syncthreads();
    for (int off = 1; off < 1024; off <<= 1) {
        unsigned v = part[tid];
        unsigned add = (tid >= off) ? part[tid - off] : 0u;
        __syncthreads();
        part[tid] = v + add;
        __syncthreads();
    }
    unsigned cum = part[tid] - s;
    #pragma unroll
    for (int q = 0; q < 4; q++) {
        unsigned prev = cum;
        cum += local[q];
        if (prev < (unsigned)KTOP && cum >= (unsigned)KTOP) {
            g_tb[img] = NBINS - 1 - (tid * 4 + q);
        }
    }
}

// -------- kernel 3: select + sort + decode + class bucketing --------
__global__ void __launch_bounds__(1024) k_prep(const float* __restrict__ reg,
                                               const float* __restrict__ anc) {
    extern __shared__ unsigned char dyn[];
    unsigned long long* sb  = (unsigned long long*)dyn;               // [SORTN]
    unsigned long long* bnd = (unsigned long long*)(dyn + SORTN * 8); // [BNDC]
    int* lbv = (int*)(dyn + SORTN * 8);                               // aliases bnd (after phase2)

    __shared__ int s_n, s_b, s_sub, s_st, s_nab;
    __shared__ unsigned h2[256], p2[256];
    __shared__ unsigned long long subarr[SUBC];

    int img = blockIdx.x;
    int tid = threadIdx.x;
    int warp = tid >> 5, lane = tid & 31;
    if (tid == 0) { s_n = 0; s_b = 0; s_sub = 0; s_st = -1; s_nab = 0; }
    if (tid < 256) h2[tid] = 0u;
    for (int i = tid; i < SORTN; i += 1024) sb[i] = 0ULL;
    __syncthreads();

    // Phase 1: definite (bin > tb) -> sb; boundary (bin == tb) -> bnd
    int C = g_cnt[img]; if (C > CAPC) C = CAPC;
    unsigned tb = (unsigned)g_tb[img];
    for (int i = tid; i < C; i += 1024) {
        unsigned long long cd = g_cand[img][i];
        unsigned key = (unsigned)(cd >> 32);
        unsigned bin = key >> 20;
        if (bin > tb) {
            int pos = atomicAdd(&s_n, 1);
            if (pos < SORTN) sb[pos] = cd;
        } else if (bin == tb) {
            int bp = atomicAdd(&s_b, 1);
            if (bp < BNDC) {
                bnd[bp] = cd;
                atomicAdd(&h2[(key >> 12) & 0xFFu], 1u);
            }
        }
    }
    __syncthreads();

    // Phase 2: sub-bin refine within boundary bin
    int n_def = s_n; if (n_def > SORTN) n_def = SORTN;
    int need = KTOP - n_def; if (need < 0) need = 0;
    int nb = s_b; if (nb > BNDC) nb = BNDC;
    unsigned myv = 0;
    if (tid < 256) { myv = h2[255 - tid]; p2[tid] = myv; }
    __syncthreads();
    for (int off = 1; off < 256; off <<= 1) {
        unsigned v = 0, add = 0;
        if (tid < 256) { v = p2[tid]; if (tid >= off) add = p2[tid - off]; }
        __syncthreads();
        if (tid < 256) p2[tid] = v + add;
        __syncthreads();
    }
    if (need > 0 && tid < 256) {
        unsigned cum = p2[tid];
        unsigned prev = cum - myv;
        if (prev < (unsigned)need && cum >= (unsigned)need) {
            s_st = 255 - tid;
            s_nab = (int)prev;
        }
    }
    __syncthreads();
    int st = s_st, nab = s_nab;
    int need_sub = need - nab;
    if (need > 0) {
        for (int i = tid; i < nb; i += 1024) {
            unsigned long long cd = bnd[i];
            int sub = (int)(((unsigned)(cd >> 32) >> 12) & 0xFFu);
            if (sub > st) {
                int pos = atomicAdd(&s_n, 1);
                if (pos < SORTN) sb[pos] = cd;
            } else if (sub == st) {
                int q = atomicAdd(&s_sub, 1);
                if (q < SUBC) subarr[q] = cd;
            }
        }
        __syncthreads();
        int ms = s_sub; if (ms > SUBC) ms = SUBC;
        for (int i = tid; i < ms; i += 1024) {
            unsigned long long cd = subarr[i];
            int r = 0;
            for (int k = 0; k < ms; k++) r += (subarr[k] > cd) ? 1 : 0;
            if (r < need_sub) {
                int pos = atomicAdd(&s_n, 1);
                if (pos < SORTN) sb[pos] = cd;
            }
        }
    }
    __syncthreads();

    // bitonic sort descending over SORTN (pads = 0 sink to the bottom)
    for (int kk = 2; kk <= SORTN; kk <<= 1) {
        for (int jj = kk >> 1; jj > 0; jj >>= 1) {
            for (int i = tid; i < SORTN; i += 1024) {
                int l = i ^ jj;
                if (l > i) {
                    unsigned long long a = sb[i], b = sb[l];
                    bool desc = ((i & kk) == 0);
                    if (desc ? (a < b) : (a > b)) { sb[i] = b; sb[l] = a; }
                }
            }
            __syncthreads();
        }
    }

    // decode top-KTOP in sorted (descending) order -> global arrays (+ smem labels)
    for (int i = tid; i < KTOP; i += 1024) {
        unsigned long long cd = sb[i];
        unsigned key = (unsigned)(cd >> 32);
        g_surv[img][i] = 0;
        if (key == 0u) {
            gbx1[img][i] = 0.f; gby1[img][i] = 0.f; gbx2[img][i] = 0.f; gby2[img][i] = 0.f;
            gbar[img][i] = 0.f; gbso[img][i] = 0.f; gblb[img][i] = -1; lbv[i] = -1;
            continue;
        }
        unsigned e = 0xFFFFFFFFu - (unsigned)(cd & 0xFFFFFFFFu);
        int labv = (int)(e % C_CLS);
        int bidx = (int)(e / C_CLS);
        float logit = keyfloat(key);
        float score = 1.f / (1.f + expf(-logit));
        float4 A = *(const float4*)(anc + ((size_t)img * M_ANCH + bidx) * 4);
        float4 R = *(const float4*)(reg + ((size_t)img * M_ANCH + bidx) * 4);
        float wdt = A.z - A.x + 1.f;
        float hgt = A.w - A.y + 1.f;
        float cx = A.x + 0.5f * wdt;
        float cy = A.y + 0.5f * hgt;
        float dx = R.x / 10.f;
        float dy = R.y / 10.f;
        float dw = fminf(R.z / 5.f, BBOX_CLIP);
        float dh = fminf(R.w / 5.f, BBOX_CLIP);
        float pcx = dx * wdt + cx;
        float pcy = dy * hgt + cy;
        float pw = expf(dw) * wdt;
        float ph = expf(dh) * hgt;
        float bx1 = pcx - 0.5f * pw;
        float by1 = pcy - 0.5f * ph;
        float bx2 = pcx + 0.5f * pw - 1.f;
        float by2 = pcy + 0.5f * ph - 1.f;
        gbx1[img][i] = bx1; gby1[img][i] = by1; gbx2[img][i] = bx2; gby2[img][i] = by2;
        gbar[img][i] = fmaxf(bx2 - bx1, 0.f) * fmaxf(by2 - by1, 0.f);
        gbso[img][i] = score;
        int lb = (score > 0.05f) ? labv : -1;
        gblb[img][i] = lb;
        lbv[i] = lb;
    }
    __syncthreads();

    // stable class bucketing: one warp per class (order-preserving ballot scan)
    for (int c = warp; c < C_CLS; c += 32) {
        int cnt = 0;
        for (int base = 0; base < KTOP; base += 32) {
            bool m = (lbv[base + lane] == c);
            unsigned bal = __ballot_sync(0xFFFFFFFFu, m);
            if (m) {
                int rk = __popc(bal & ((1u << lane) - 1u));
                int pos = cnt + rk;
                if (pos < CCAP) g_cl[img][c][pos] = (unsigned short)(base + lane);
            }
            cnt += __popc(bal);
        }
        if (lane == 0) g_ccnt[img][c] = (cnt < CCAP) ? cnt : CCAP;
    }
}

// -------- kernel 4: one warp-block per (class, image) greedy NMS --------
__global__ void __launch_bounds__(32) k_nms2() {
    int c   = blockIdx.x;
    int img = blockIdx.y;
    int lane = threadIdx.x;
    int m = g_ccnt[img][c];
    if (m == 0) return;

    __shared__ float sx1[CCAP], sy1[CCAP], sx2[CCAP], sy2[CCAP], sar[CCAP];
    __shared__ unsigned short sid[CCAP];

    for (int p = lane; p < m; p += 32) {
        int i = (int)g_cl[img][c][p];
        sid[p] = (unsigned short)i;
        sx1[p] = gbx1[img][i]; sy1[p] = gby1[img][i];
        sx2[p] = gbx2[img][i]; sy2[p] = gby2[img][i];
        sar[p] = gbar[img][i];
    }
    __syncwarp();

    // registers: item p = lane + 32*r
    float lx1[RPC], ly1[RPC], lx2[RPC], ly2[RPC], lar[RPC];
    unsigned alive = 0u;
    #pragma unroll
    for (int r = 0; r < RPC; r++) {
        int p = lane + 32 * r;
        lx1[r] = 0.f; ly1[r] = 0.f; lx2[r] = 0.f; ly2[r] = 0.f; lar[r] = 0.f;
        if (p < m) {
            lx1[r] = sx1[p]; ly1[r] = sy1[p];
            lx2[r] = sx2[p]; ly2[r] = sy2[p];
            lar[r] = sar[p];
            alive |= (1u << r);
        }
    }

    while (true) {
        unsigned myp = alive ? (unsigned)(lane + 32 * (__ffs(alive) - 1)) : 0xFFFFFFFFu;
        unsigned wmin = __reduce_min_sync(0xFFFFFFFFu, myp);
        if (wmin == 0xFFFFFFFFu) break;
        int psel = (int)wmin;
        // broadcast selected coords via uniform LDS
        float bx1 = sx1[psel], by1 = sy1[psel];
        float bx2 = sx2[psel], by2 = sy2[psel];
        float bar = sar[psel];
        if (lane == (psel & 31)) {
            alive &= ~(1u << (psel >> 5));
            g_surv[img][sid[psel]] = 1;
        }
        #pragma unroll
        for (int r = 0; r < RPC; r++) {
            if (alive & (1u << r)) {
                float xx1 = fmaxf(bx1, lx1[r]);
                float yy1 = fmaxf(by1, ly1[r]);
                float xx2 = fminf(bx2, lx2[r]);
                float yy2 = fminf(by2, ly2[r]);
                float inter = fmaxf(xx2 - xx1, 0.f) * fmaxf(yy2 - yy1, 0.f);
                float iou = inter / (bar + lar[r] - inter + 1e-6f);
                if (iou > 0.5f) alive &= ~(1u << r);
            }
        }
    }
}

// -------- kernel 5: stable compact survivors + output --------
#define OUTT 128
#define OIPT ((KTOP + OUTT - 1) / OUTT)   // 32 (last thread partial)
__global__ void __launch_bounds__(OUTT) k_out(const int* __restrict__ sizes,
                                              float* __restrict__ out) {
    __shared__ int ps[OUTT];
    __shared__ int keepj[POST];
    __shared__ int s_tot;

    int img = blockIdx.x;
    int tid = threadIdx.x;

    unsigned char sv[OIPT];
    int cnt = 0;
    #pragma unroll
    for (int k = 0; k < OIPT; k++) {
        int i = tid * OIPT + k;
        sv[k] = (i < KTOP) ? g_surv[img][i] : 0;
        if (sv[k]) cnt++;
    }
    ps[tid] = cnt;
    __syncthreads();
    for (int off = 1; off < OUTT; off <<= 1) {
        int v = ps[tid];
        int add = (tid >= off) ? ps[tid - off] : 0;
        __syncthreads();
        ps[tid] = v + add;
        __syncthreads();
    }
    int rk = ps[tid] - cnt;
    #pragma unroll
    for (int k = 0; k < OIPT; k++) {
        if (sv[k]) {
            if (rk < POST) keepj[rk] = tid * OIPT + k;
            rk++;
        }
    }
    if (tid == OUTT - 1) {
        int tot = ps[OUTT - 1];
        s_tot = (tot < POST) ? tot : POST;
    }
    __syncthreads();

    // outputs: boxes[4,100,4] | scores[4,100] | classes[4,100] | num[4]
    float wImg = (float)sizes[img * 2 + 0];
    float hImg = (float)sizes[img * 2 + 1];
    if (tid < POST) {
        int t = tid;
        int ok = (t < s_tot) ? 1 : 0;
        float b0, b1, b2, b3, s, c;
        if (ok) {
            int j = keepj[t];
            b0 = fminf(fmaxf(gbx1[img][j], 0.f), wImg - 1.f);
            b1 = fminf(fmaxf(gby1[img][j], 0.f), hImg - 1.f);
            b2 = fminf(fmaxf(gbx2[img][j], 0.f), wImg - 1.f);
            b3 = fminf(fmaxf(gby2[img][j], 0.f), hImg - 1.f);
            s = gbso[img][j];
            c = (float)(gblb[img][j] + 1);
        } else {
            b0 = b1 = b2 = b3 = 0.f; s = 0.f; c = -1.f;
        }
        float* ob = out + (size_t)img * POST * 4;
        ob[t * 4 + 0] = b0; ob[t * 4 + 1] = b1; ob[t * 4 + 2] = b2; ob[t * 4 + 3] = b3;
        out[N_IMG * POST * 4 + img * POST + t] = s;
        out[N_IMG * POST * 4 + N_IMG * POST + img * POST + t] = c;
    }
    if (tid == 0) {
        out[N_IMG * POST * 4 + 2 * N_IMG * POST + img] = (float)s_tot;
    }
}

extern "C" void kernel_launch(void* const* d_in, const int* in_sizes, int n_in,
                              void* d_out, int out_size) {
    const float* cls  = (const float*)d_in[0];
    const float* regr = (const float*)d_in[1];
    const float* anch = (const float*)d_in[2];
    const int*   szs  = (const int*)d_in[3];
    float* out = (float*)d_out;

    static bool attr_done = false;
    if (!attr_done) {
        cudaFuncSetAttribute(k_prep, cudaFuncAttributeMaxDynamicSharedMemorySize, PREP_SMEM);
        attr_done = true;
    }

    k_zero<<<(N_IMG * NBINS + 255) / 256, 256>>>();
    k_scan<<<dim3(74, N_IMG), 1024>>>((const uint4*)cls);
    k_sel<<<N_IMG, 1024>>>();
    k_prep<<<N_IMG, 1024, PREP_SMEM>>>(regr, anch);
    k_nms2<<<dim3(C_CLS, N_IMG), 32>>>();
    k_out<<<N_IMG, OUTT>>>(szs, out);
}